// round 7
// baseline (speedup 1.0000x reference)
#include <cuda_runtime.h>
#include <cuda_bf16.h>

#define H 256
#define D 8
#define BN_EPS 1e-5f
#define MAXE 500000

typedef unsigned long long u64;
typedef unsigned int u32;

// ---------------- packed f32x2 helpers ----------------
__device__ __forceinline__ u64 ffma2(u64 a, u64 b, u64 c) {
    u64 d; asm("fma.rn.f32x2 %0, %1, %2, %3;" : "=l"(d) : "l"(a), "l"(b), "l"(c)); return d;
}
__device__ __forceinline__ u64 fadd2(u64 a, u64 b) {
    u64 d; asm("add.rn.f32x2 %0, %1, %2;" : "=l"(d) : "l"(a), "l"(b)); return d;
}
__device__ __forceinline__ u64 pack2(float lo, float hi) {
    u64 d; asm("mov.b64 %0, {%1, %2};" : "=l"(d) : "f"(lo), "f"(hi)); return d;
}
__device__ __forceinline__ float2 unpack2(u64 v) {
    float lo, hi; asm("mov.b64 {%0, %1}, %2;" : "=f"(lo), "=f"(hi) : "l"(v));
    return make_float2(lo, hi);
}
__device__ __forceinline__ u64 abs2(u64 v) {
    u64 d; asm("and.b64 %0, %1, 0x7FFFFFFF7FFFFFFF;" : "=l"(d) : "l"(v)); return d;
}
// relu2x: returns 2*relu per lane (q + |q|)
__device__ __forceinline__ u64 relu2x(u64 q) { return fadd2(q, abs2(q)); }

// ---------------- device scratch (static, allocation-free) ----------------
__device__ float g_P [H * D];
__device__ float g_T2[H * D];
__device__ float g_M [H * D];
__device__ float g_c [D];
__device__ float g_sum  [H];
__device__ float g_sumsq[H];
__device__ float g_Ms[H * D];   // 0.25 * diag(s) @ M
__device__ float g_c8[D];       // 0.5 * (t @ M + c)
__device__ __nv_bfloat16 g_h[(size_t)MAXE * H];   // cached r = 2*relu(q), 256 MB

// ---------------- fold kernels ----------------
__global__ void k_fold1(const float* __restrict__ Wo, const float* __restrict__ Wp) {
    int t = blockIdx.x * blockDim.x + threadIdx.x;
    int i = t >> 3, d = t & 7;
    float acc = 0.f;
#pragma unroll 8
    for (int k = 0; k < H; k++) acc = fmaf(Wo[i * H + k], Wp[k * D + d], acc);
    g_P[i * D + d] = acc;
    if (t < H) { g_sum[t] = 0.f; g_sumsq[t] = 0.f; }
}

__global__ void k_fold2(const float* __restrict__ Wv) {
    int t = blockIdx.x * blockDim.x + threadIdx.x;
    int i = t >> 3, d = t & 7;
    float acc = 0.f;
#pragma unroll 8
    for (int k = 0; k < H; k++) acc = fmaf(Wv[i * H + k], g_P[k * D + d], acc);
    g_T2[i * D + d] = acc;
}

__global__ void k_fold3(const float* __restrict__ W2, const float* __restrict__ b2,
                        const float* __restrict__ bv, const float* __restrict__ bo,
                        const float* __restrict__ bp, const float* __restrict__ Wp) {
    int t = blockIdx.x * blockDim.x + threadIdx.x;
    int i = t >> 3, d = t & 7;
    float acc = 0.f;
#pragma unroll 8
    for (int k = 0; k < H; k++) acc = fmaf(W2[i * H + k], g_T2[k * D + d], acc);
    g_M[i * D + d] = acc;
    if (t < D) {
        float c = bp[t];
        for (int k = 0; k < H; k++) {
            c = fmaf(b2[k], g_T2[k * D + t], c);
            c = fmaf(bv[k], g_P [k * D + t], c);
            c = fmaf(bo[k], Wp  [k * D + t], c);
        }
        g_c[t] = c;
    }
}

// ---------------- pass 1: stats of h = relu(nc@W1+b1); optionally store r=2h (bf16) ----------
template<bool STORE>
__global__ void __launch_bounds__(256) k_pass1(
    const float* __restrict__ nf, const int* __restrict__ ei,
    const float* __restrict__ W1, const float* __restrict__ b1, int E) {
    __shared__ __align__(16) float ncsT[8][256];     // [k][edge-in-tile]
    const int t = threadIdx.x;

    u64 w2[8];
#pragma unroll
    for (int k = 0; k < 8; k++) { float w = W1[k * H + t]; w2[k] = pack2(w, w); }
    const float bb = b1[t];
    const u64 b2p = pack2(bb, bb);

    u64 sumA = pack2(0.f, 0.f), ssqA = sumA, sumB = sumA, ssqB = sumA;
    const int numTiles = (E + 255) >> 8;

    for (int tile = blockIdx.x; tile < numTiles; tile += gridDim.x) {
        const int base = tile << 8;
        const int cnt  = min(256, E - base);
        __syncthreads();
        if (t < cnt) {
            const int e  = base + t;
            const int s0 = ei[e];
            const int s1 = ei[E + e];
            const float4* a = (const float4*)(nf + (size_t)s0 * D);
            const float4* b = (const float4*)(nf + (size_t)s1 * D);
            float4 x0 = a[0], x1 = a[1], y0 = b[0], y1 = b[1];
            ncsT[0][t] = 0.5f * (x0.x + y0.x);
            ncsT[1][t] = 0.5f * (x0.y + y0.y);
            ncsT[2][t] = 0.5f * (x0.z + y0.z);
            ncsT[3][t] = 0.5f * (x0.w + y0.w);
            ncsT[4][t] = 0.5f * (x1.x + y1.x);
            ncsT[5][t] = 0.5f * (x1.y + y1.y);
            ncsT[6][t] = 0.5f * (x1.z + y1.z);
            ncsT[7][t] = 0.5f * (x1.w + y1.w);
        }
        __syncthreads();
        int e = 0;
        for (; e + 3 < cnt; e += 4) {
            u64 q0 = b2p, q1 = b2p;
#pragma unroll
            for (int k = 0; k < 8; k++) {
                ulonglong2 n = *(const ulonglong2*)&ncsT[k][e];
                q0 = ffma2(n.x, w2[k], q0);
                q1 = ffma2(n.y, w2[k], q1);
            }
            u64 r0 = relu2x(q0);
            u64 r1 = relu2x(q1);
            sumA = fadd2(sumA, r0);      sumB = fadd2(sumB, r1);
            ssqA = ffma2(r0, r0, ssqA);  ssqB = ffma2(r1, r1, ssqB);
            if (STORE) {
                float2 f0 = unpack2(r0), f1 = unpack2(r1);
                __nv_bfloat16* hp = g_h + (size_t)(base + e) * H + t;
                hp[0]     = __float2bfloat16_rn(f0.x);
                hp[H]     = __float2bfloat16_rn(f0.y);
                hp[2 * H] = __float2bfloat16_rn(f1.x);
                hp[3 * H] = __float2bfloat16_rn(f1.y);
            }
        }
        for (; e + 1 < cnt; e += 2) {
            u64 q0 = b2p;
#pragma unroll
            for (int k = 0; k < 8; k++)
                q0 = ffma2(*(const u64*)&ncsT[k][e], w2[k], q0);
            u64 r0 = relu2x(q0);
            sumA = fadd2(sumA, r0);
            ssqA = ffma2(r0, r0, ssqA);
            if (STORE) {
                float2 f0 = unpack2(r0);
                __nv_bfloat16* hp = g_h + (size_t)(base + e) * H + t;
                hp[0] = __float2bfloat16_rn(f0.x);
                hp[H] = __float2bfloat16_rn(f0.y);
            }
        }
        if (e < cnt) {                        // odd tail: hi lane poisoned -> r=0
            u64 q0 = pack2(bb, -1e30f);
#pragma unroll
            for (int k = 0; k < 8; k++)
                q0 = ffma2(pack2(ncsT[k][e], 0.f), w2[k], q0);
            u64 r0 = relu2x(q0);
            sumA = fadd2(sumA, r0);
            ssqA = ffma2(r0, r0, ssqA);
            if (STORE) {
                float2 f0 = unpack2(r0);
                g_h[(size_t)(base + e) * H + t] = __float2bfloat16_rn(f0.x);
            }
        }
    }
    float2 sa = unpack2(fadd2(sumA, sumB));
    float2 qa = unpack2(fadd2(ssqA, ssqB));
    atomicAdd(&g_sum[t],   sa.x + sa.y);
    atomicAdd(&g_sumsq[t], qa.x + qa.y);
}

// ---------------- finalize ----------------
__global__ void k_finalize(const float* __restrict__ gamma,
                           const float* __restrict__ beta, float invE) {
    __shared__ float tvs[H];
    const int j = threadIdx.x;
    float mu  = 0.5f  * g_sum[j]   * invE;
    float eh2 = 0.25f * g_sumsq[j] * invE;
    float var = fmaf(-mu, mu, eh2);
    float s   = gamma[j] * rsqrtf(var + BN_EPS);
    float tv  = fmaf(-mu, s, beta[j]);
#pragma unroll
    for (int d = 0; d < D; d++) g_Ms[j * D + d] = 0.25f * s * g_M[j * D + d];
    tvs[j] = tv;
    __syncthreads();
    if (j < D) {
        float acc = g_c[j];
        for (int k = 0; k < H; k++) acc = fmaf(tvs[k], g_M[k * D + j], acc);
        g_c8[j] = 0.5f * acc;
    }
}

// ---------------- pass 2 (cached): out = ea + (r_bf16 @ Ms025) + c8 ----------------
// 3 edges/thread, 128-thread blocks; r streamed from g_h; only Ms from smem.
__global__ void __launch_bounds__(128) k_pass2c(
    const float* __restrict__ ea, float* __restrict__ out, int E) {
    __shared__ __align__(16) u64 ms2p[128 * 8];   // [jp][d] = (Ms[2jp][d], Ms[2jp+1][d])
    __shared__ float c8s[D];

    const int t = threadIdx.x;
    for (int idx = t; idx < 128 * 8; idx += 128) {
        int jp = idx >> 3, k = idx & 7;
        ms2p[idx] = pack2(g_Ms[(2 * jp) * D + k], g_Ms[(2 * jp + 1) * D + k]);
    }
    if (t < D) c8s[t] = g_c8[t];
    __syncthreads();

    int eidx[3]; bool val[3];
#pragma unroll
    for (int i = 0; i < 3; i++) {
        int er = blockIdx.x * 384 + i * 128 + t;
        val[i]  = er < E;
        eidx[i] = val[i] ? er : 0;
    }

    const uint4* hb = (const uint4*)g_h;   // 1 uint4 = 8 bf16 cols = 4 col-pairs
    size_t hbase[3];
#pragma unroll
    for (int i = 0; i < 3; i++) hbase[i] = (size_t)eidx[i] * (H / 8);

    u64 acc[3][8];
    const u64 z = pack2(0.f, 0.f);
#pragma unroll
    for (int i = 0; i < 3; i++)
#pragma unroll
        for (int d = 0; d < 8; d++) acc[i][d] = z;

    uint4 cur[3];
#pragma unroll
    for (int i = 0; i < 3; i++) cur[i] = hb[hbase[i]];

#pragma unroll 1
    for (int jb = 0; jb < 32; jb++) {
        uint4 nxt[3];
        if (jb < 31) {
#pragma unroll
            for (int i = 0; i < 3; i++) nxt[i] = hb[hbase[i] + jb + 1];
        }
#pragma unroll
        for (int sub = 0; sub < 4; sub++) {
            const int jp = jb * 4 + sub;
            u64 m8[8];
            {
                ulonglong2 v0 = *(const ulonglong2*)&ms2p[jp * 8 + 0];
                ulonglong2 v1 = *(const ulonglong2*)&ms2p[jp * 8 + 2];
                ulonglong2 v2 = *(const ulonglong2*)&ms2p[jp * 8 + 4];
                ulonglong2 v3 = *(const ulonglong2*)&ms2p[jp * 8 + 6];
                m8[0] = v0.x; m8[1] = v0.y; m8[2] = v1.x; m8[3] = v1.y;
                m8[4] = v2.x; m8[5] = v2.y; m8[6] = v3.x; m8[7] = v3.y;
            }
#pragma unroll
            for (int i = 0; i < 3; i++) {
                u32 w = (sub == 0) ? cur[i].x : (sub == 1) ? cur[i].y
                      : (sub == 2) ? cur[i].z : cur[i].w;
                float lo = __uint_as_float(w << 16);
                float hi = __uint_as_float(w & 0xFFFF0000u);
                u64 h2 = pack2(lo, hi);
#pragma unroll
                for (int d = 0; d < 8; d++)
                    acc[i][d] = ffma2(h2, m8[d], acc[i][d]);
            }
        }
#pragma unroll
        for (int i = 0; i < 3; i++) cur[i] = nxt[i];
    }

#pragma unroll
    for (int i = 0; i < 3; i++) {
        if (!val[i]) continue;
        const float4* eap = (const float4*)(ea + (size_t)eidx[i] * D);
        float4 i0 = eap[0], i1 = eap[1];
        float o[8];
#pragma unroll
        for (int d = 0; d < 8; d++) {
            float2 p = unpack2(acc[i][d]);
            o[d] = p.x + p.y + c8s[d];
        }
        float4 o0 = make_float4(i0.x + o[0], i0.y + o[1], i0.z + o[2], i0.w + o[3]);
        float4 o1 = make_float4(i1.x + o[4], i1.y + o[5], i1.z + o[6], i1.w + o[7]);
        float4* op = (float4*)(out + (size_t)eidx[i] * D);
        op[0] = o0; op[1] = o1;
    }
}

// ---------------- pass 2 fallback (recompute; only if E > MAXE) ----------------
__global__ void __launch_bounds__(128) k_pass2_fb(
    const float* __restrict__ ea, const float* __restrict__ nf,
    const int* __restrict__ ei,
    const float* __restrict__ W1, const float* __restrict__ b1,
    float* __restrict__ out, int E) {
    __shared__ __align__(16) u64 w2p [128 * 8];
    __shared__ __align__(16) u64 ms2p[128 * 8];
    __shared__ u64 b2ps[128];
    __shared__ float c8s[D];

    const int t = threadIdx.x;
    for (int idx = t; idx < 128 * 8; idx += 128) {
        int jp = idx >> 3, k = idx & 7;
        w2p [idx] = pack2(W1[k * H + 2 * jp], W1[k * H + 2 * jp + 1]);
        ms2p[idx] = pack2(g_Ms[(2 * jp) * D + k], g_Ms[(2 * jp + 1) * D + k]);
    }
    b2ps[t] = pack2(b1[2 * t], b1[2 * t + 1]);
    if (t < D) c8s[t] = g_c8[t];
    __syncthreads();

    int eidx[3]; bool val[3];
#pragma unroll
    for (int i = 0; i < 3; i++) {
        int er = blockIdx.x * 384 + i * 128 + t;
        val[i]  = er < E;
        eidx[i] = val[i] ? er : E - 1;
    }
    u64 nc[3][8];
#pragma unroll
    for (int i = 0; i < 3; i++) {
        const int s0 = ei[eidx[i]];
        const int s1 = ei[E + eidx[i]];
        const float4* p0 = (const float4*)(nf + (size_t)s0 * D);
        const float4* p1 = (const float4*)(nf + (size_t)s1 * D);
        float4 x0 = p0[0], x1 = p0[1], y0 = p1[0], y1 = p1[1];
        float n[8];
        n[0] = 0.5f * (x0.x + y0.x); n[1] = 0.5f * (x0.y + y0.y);
        n[2] = 0.5f * (x0.z + y0.z); n[3] = 0.5f * (x0.w + y0.w);
        n[4] = 0.5f * (x1.x + y1.x); n[5] = 0.5f * (x1.y + y1.y);
        n[6] = 0.5f * (x1.z + y1.z); n[7] = 0.5f * (x1.w + y1.w);
#pragma unroll
        for (int k = 0; k < 8; k++) nc[i][k] = pack2(n[k], n[k]);
    }
    u64 acc[3][8];
    const u64 z = pack2(0.f, 0.f);
#pragma unroll
    for (int i = 0; i < 3; i++)
#pragma unroll
        for (int d = 0; d < 8; d++) acc[i][d] = z;

#pragma unroll 1
    for (int jp = 0; jp < 128; jp++) {
        u64 w8[8];
        {
            ulonglong2 v0 = *(const ulonglong2*)&w2p[jp * 8 + 0];
            ulonglong2 v1 = *(const ulonglong2*)&w2p[jp * 8 + 2];
            ulonglong2 v2 = *(const ulonglong2*)&w2p[jp * 8 + 4];
            ulonglong2 v3 = *(const ulonglong2*)&w2p[jp * 8 + 6];
            w8[0] = v0.x; w8[1] = v0.y; w8[2] = v1.x; w8[3] = v1.y;
            w8[4] = v2.x; w8[5] = v2.y; w8[6] = v3.x; w8[7] = v3.y;
        }
        const u64 bp = b2ps[jp];
        u64 q0 = bp, q1 = bp, q2 = bp;
#pragma unroll
        for (int k = 0; k < 8; k++) {
            q0 = ffma2(nc[0][k], w8[k], q0);
            q1 = ffma2(nc[1][k], w8[k], q1);
            q2 = ffma2(nc[2][k], w8[k], q2);
        }
        u64 r0 = relu2x(q0), r1 = relu2x(q1), r2 = relu2x(q2);
        u64 m8[8];
        {
            ulonglong2 v0 = *(const ulonglong2*)&ms2p[jp * 8 + 0];
            ulonglong2 v1 = *(const ulonglong2*)&ms2p[jp * 8 + 2];
            ulonglong2 v2 = *(const ulonglong2*)&ms2p[jp * 8 + 4];
            ulonglong2 v3 = *(const ulonglong2*)&ms2p[jp * 8 + 6];
            m8[0] = v0.x; m8[1] = v0.y; m8[2] = v1.x; m8[3] = v1.y;
            m8[4] = v2.x; m8[5] = v2.y; m8[6] = v3.x; m8[7] = v3.y;
        }
#pragma unroll
        for (int d = 0; d < 8; d++) {
            acc[0][d] = ffma2(r0, m8[d], acc[0][d]);
            acc[1][d] = ffma2(r1, m8[d], acc[1][d]);
            acc[2][d] = ffma2(r2, m8[d], acc[2][d]);
        }
    }
#pragma unroll
    for (int i = 0; i < 3; i++) {
        if (!val[i]) continue;
        const float4* eap = (const float4*)(ea + (size_t)eidx[i] * D);
        float4 i0 = eap[0], i1 = eap[1];
        float o[8];
#pragma unroll
        for (int d = 0; d < 8; d++) {
            float2 p = unpack2(acc[i][d]);
            o[d] = p.x + p.y + c8s[d];
        }
        float4 o0 = make_float4(i0.x + o[0], i0.y + o[1], i0.z + o[2], i0.w + o[3]);
        float4 o1 = make_float4(i1.x + o[4], i1.y + o[5], i1.z + o[6], i1.w + o[7]);
        float4* op = (float4*)(out + (size_t)eidx[i] * D);
        op[0] = o0; op[1] = o1;
    }
}

// ---------------- launcher ----------------
extern "C" void kernel_launch(void* const* d_in, const int* in_sizes, int n_in,
                              void* d_out, int out_size) {
    const float* edge_attr     = (const float*)d_in[0];
    const float* node_features = (const float*)d_in[1];
    const int*   edge_index    = (const int*)  d_in[2];
    const float* n_W1    = (const float*)d_in[9];
    const float* n_b1    = (const float*)d_in[10];
    const float* n_gamma = (const float*)d_in[11];
    const float* n_beta  = (const float*)d_in[12];
    const float* n_W2    = (const float*)d_in[13];
    const float* n_b2    = (const float*)d_in[14];
    const float* Wv      = (const float*)d_in[15];
    const float* bv      = (const float*)d_in[16];
    const float* Wo      = (const float*)d_in[17];
    const float* bo      = (const float*)d_in[18];
    const float* Wp      = (const float*)d_in[19];
    const float* bp      = (const float*)d_in[20];

    const int E = in_sizes[0] / D;
    float* out = (float*)d_out;

    k_fold1<<<16, 128>>>(Wo, Wp);
    k_fold2<<<16, 128>>>(Wv);
    k_fold3<<<16, 128>>>(n_W2, n_b2, bv, bo, bp, Wp);
    if (E <= MAXE) {
        k_pass1<true><<<1184, 256>>>(node_features, edge_index, n_W1, n_b1, E);
        k_finalize<<<1, 256>>>(n_gamma, n_beta, 1.0f / (float)E);
        k_pass2c<<<(E + 383) / 384, 128>>>(edge_attr, out, E);
    } else {
        k_pass1<false><<<1184, 256>>>(node_features, edge_index, n_W1, n_b1, E);
        k_finalize<<<1, 256>>>(n_gamma, n_beta, 1.0f / (float)E);
        k_pass2_fb<<<(E + 383) / 384, 128>>>(edge_attr, node_features, edge_index,
                                             n_W1, n_b1, out, E);
    }
}

// round 8
// speedup vs baseline: 1.1597x; 1.1597x over previous
#include <cuda_runtime.h>

#define H 256
#define D 8
#define BN_EPS 1e-5f

typedef unsigned long long u64;

// ---------------- packed f32x2 helpers ----------------
__device__ __forceinline__ u64 ffma2(u64 a, u64 b, u64 c) {
    u64 d; asm("fma.rn.f32x2 %0, %1, %2, %3;" : "=l"(d) : "l"(a), "l"(b), "l"(c)); return d;
}
__device__ __forceinline__ u64 fadd2(u64 a, u64 b) {
    u64 d; asm("add.rn.f32x2 %0, %1, %2;" : "=l"(d) : "l"(a), "l"(b)); return d;
}
__device__ __forceinline__ u64 pack2(float lo, float hi) {
    u64 d; asm("mov.b64 %0, {%1, %2};" : "=l"(d) : "f"(lo), "f"(hi)); return d;
}
__device__ __forceinline__ float2 unpack2(u64 v) {
    float lo, hi; asm("mov.b64 {%0, %1}, %2;" : "=f"(lo), "=f"(hi) : "l"(v));
    return make_float2(lo, hi);
}
__device__ __forceinline__ u64 abs2(u64 v) {
    u64 d; asm("and.b64 %0, %1, 0x7FFFFFFF7FFFFFFF;" : "=l"(d) : "l"(v)); return d;
}
// relu2x: returns 2*relu per lane (q + |q|)
__device__ __forceinline__ u64 relu2x(u64 q) { return fadd2(q, abs2(q)); }

// ---------------- device scratch (static, allocation-free) ----------------
__device__ float g_P [H * D];   // Wo @ Wp
__device__ float g_T2[H * D];   // Wv @ P
__device__ float g_M [H * D];   // W2 @ T2
__device__ float g_c [D];       // folded bias chain
__device__ float g_sum  [H];    // per-column sum of r = 2h
__device__ float g_sumsq[H];    // per-column sum of r^2 = 4h^2
__device__ float g_Ms[H * D];   // 0.25 * diag(s) @ M
__device__ float g_c8[D];       // 0.5 * (t @ M + c)

// ---------------- fold kernels (tiny, R4-proven) ----------------
__global__ void k_fold1(const float* __restrict__ Wo, const float* __restrict__ Wp) {
    int t = blockIdx.x * blockDim.x + threadIdx.x;   // 0..2047
    int i = t >> 3, d = t & 7;
    float acc = 0.f;
#pragma unroll 8
    for (int k = 0; k < H; k++) acc = fmaf(Wo[i * H + k], Wp[k * D + d], acc);
    g_P[i * D + d] = acc;
    if (t < H) { g_sum[t] = 0.f; g_sumsq[t] = 0.f; }
}

__global__ void k_fold2(const float* __restrict__ Wv) {
    int t = blockIdx.x * blockDim.x + threadIdx.x;
    int i = t >> 3, d = t & 7;
    float acc = 0.f;
#pragma unroll 8
    for (int k = 0; k < H; k++) acc = fmaf(Wv[i * H + k], g_P[k * D + d], acc);
    g_T2[i * D + d] = acc;
}

__global__ void k_fold3(const float* __restrict__ W2, const float* __restrict__ b2,
                        const float* __restrict__ bv, const float* __restrict__ bo,
                        const float* __restrict__ bp, const float* __restrict__ Wp) {
    int t = blockIdx.x * blockDim.x + threadIdx.x;
    int i = t >> 3, d = t & 7;
    float acc = 0.f;
#pragma unroll 8
    for (int k = 0; k < H; k++) acc = fmaf(W2[i * H + k], g_T2[k * D + d], acc);
    g_M[i * D + d] = acc;
    if (t < D) {
        float c = bp[t];
        for (int k = 0; k < H; k++) {
            c = fmaf(b2[k], g_T2[k * D + t], c);
            c = fmaf(bv[k], g_P [k * D + t], c);
            c = fmaf(bo[k], Wp  [k * D + t], c);
        }
        g_c[t] = c;
    }
}

// ---------------- pass 1: batch statistics of h = relu(nc@W1 + b1) ----------------
// R4-proven: column-owner; 4 edges per iter (one LDS.128 per k); 256 threads.
__global__ void __launch_bounds__(256) k_pass1(
    const float* __restrict__ nf, const int* __restrict__ ei,
    const float* __restrict__ W1, const float* __restrict__ b1, int E) {
    __shared__ __align__(16) float ncsT[8][256];     // [k][edge-in-tile]
    const int t = threadIdx.x;

    u64 w2[8];
#pragma unroll
    for (int k = 0; k < 8; k++) { float w = W1[k * H + t]; w2[k] = pack2(w, w); }
    const float bb = b1[t];
    const u64 b2p = pack2(bb, bb);

    u64 sumA = pack2(0.f, 0.f), ssqA = sumA, sumB = sumA, ssqB = sumA;
    const int numTiles = (E + 255) >> 8;

    for (int tile = blockIdx.x; tile < numTiles; tile += gridDim.x) {
        const int base = tile << 8;
        const int cnt  = min(256, E - base);
        __syncthreads();                      // protect ncsT from prior readers
        if (t < cnt) {
            const int e  = base + t;
            const int s0 = ei[e];
            const int s1 = ei[E + e];
            const float4* a = (const float4*)(nf + (size_t)s0 * D);
            const float4* b = (const float4*)(nf + (size_t)s1 * D);
            float4 x0 = a[0], x1 = a[1], y0 = b[0], y1 = b[1];
            ncsT[0][t] = 0.5f * (x0.x + y0.x);
            ncsT[1][t] = 0.5f * (x0.y + y0.y);
            ncsT[2][t] = 0.5f * (x0.z + y0.z);
            ncsT[3][t] = 0.5f * (x0.w + y0.w);
            ncsT[4][t] = 0.5f * (x1.x + y1.x);
            ncsT[5][t] = 0.5f * (x1.y + y1.y);
            ncsT[6][t] = 0.5f * (x1.z + y1.z);
            ncsT[7][t] = 0.5f * (x1.w + y1.w);
        }
        __syncthreads();
        int e = 0;
        for (; e + 3 < cnt; e += 4) {          // 4 edges: one LDS.128 per k
            u64 q0 = b2p, q1 = b2p;
#pragma unroll
            for (int k = 0; k < 8; k++) {
                ulonglong2 n = *(const ulonglong2*)&ncsT[k][e];
                q0 = ffma2(n.x, w2[k], q0);
                q1 = ffma2(n.y, w2[k], q1);
            }
            u64 r0 = relu2x(q0);
            u64 r1 = relu2x(q1);
            sumA = fadd2(sumA, r0);      sumB = fadd2(sumB, r1);
            ssqA = ffma2(r0, r0, ssqA);  ssqB = ffma2(r1, r1, ssqB);
        }
        for (; e + 1 < cnt; e += 2) {
            u64 q0 = b2p;
#pragma unroll
            for (int k = 0; k < 8; k++)
                q0 = ffma2(*(const u64*)&ncsT[k][e], w2[k], q0);
            u64 r0 = relu2x(q0);
            sumA = fadd2(sumA, r0);
            ssqA = ffma2(r0, r0, ssqA);
        }
        if (e < cnt) {                        // odd tail: hi lane poisoned -> r=0
            u64 q0 = pack2(bb, -1e30f);
#pragma unroll
            for (int k = 0; k < 8; k++)
                q0 = ffma2(pack2(ncsT[k][e], 0.f), w2[k], q0);
            u64 r0 = relu2x(q0);
            sumA = fadd2(sumA, r0);
            ssqA = ffma2(r0, r0, ssqA);
        }
    }
    float2 sa = unpack2(fadd2(sumA, sumB));
    float2 qa = unpack2(fadd2(ssqA, ssqB));
    atomicAdd(&g_sum[t],   sa.x + sa.y);      // Σ r  (r = 2h)
    atomicAdd(&g_sumsq[t], qa.x + qa.y);      // Σ r²
}

// ---------------- finalize: fold BN affine (+relu-doubling factors) into M ----------------
__global__ void k_finalize(const float* __restrict__ gamma,
                           const float* __restrict__ beta, float invE) {
    __shared__ float tvs[H];
    const int j = threadIdx.x;
    float mu  = 0.5f  * g_sum[j]   * invE;              // E[h]
    float eh2 = 0.25f * g_sumsq[j] * invE;              // E[h^2]
    float var = fmaf(-mu, mu, eh2);                     // biased var
    float s   = gamma[j] * rsqrtf(var + BN_EPS);
    float tv  = fmaf(-mu, s, beta[j]);
#pragma unroll
    for (int d = 0; d < D; d++) g_Ms[j * D + d] = 0.25f * s * g_M[j * D + d];
    tvs[j] = tv;
    __syncthreads();
    if (j < D) {
        float acc = g_c[j];
        for (int k = 0; k < H; k++) acc = fmaf(tvs[k], g_M[k * D + j], acc);
        g_c8[j] = 0.5f * acc;
    }
}

// ---------------- pass 2: out = ea + (r @ Ms025) + c8h,  r = 2*relu(nc@W1+b1) ----------------
// edge-owner, 2 edges/thread, 128-thread blocks, min 5 blocks/SM;
// q-dot split into two independent 4-term chains to halve the RAW depth.
__global__ void __launch_bounds__(128, 5) k_pass2(
    const float* __restrict__ ea, const float* __restrict__ nf,
    const int* __restrict__ ei,
    const float* __restrict__ W1, const float* __restrict__ b1,
    float* __restrict__ out, int E) {
    __shared__ __align__(16) u64 w2p [128 * 8];   // [jp][k]  = (W1[k][2jp], W1[k][2jp+1])
    __shared__ __align__(16) u64 ms2p[128 * 8];   // [jp][d]  = (Ms[2jp][d], Ms[2jp+1][d])
    __shared__ u64 b2ps[128];                     // (b1[2jp], b1[2jp+1])
    __shared__ float c8s[D];

    const int t = threadIdx.x;
    for (int idx = t; idx < 128 * 8; idx += 128) {
        int jp = idx >> 3, k = idx & 7;
        w2p [idx] = pack2(W1[k * H + 2 * jp], W1[k * H + 2 * jp + 1]);
        ms2p[idx] = pack2(g_Ms[(2 * jp) * D + k], g_Ms[(2 * jp + 1) * D + k]);
    }
    b2ps[t] = pack2(b1[2 * t], b1[2 * t + 1]);
    if (t < D) c8s[t] = g_c8[t];
    __syncthreads();

    int eidx[2]; bool val[2];
#pragma unroll
    for (int i = 0; i < 2; i++) {
        int er = blockIdx.x * 256 + i * 128 + t;
        val[i]  = er < E;
        eidx[i] = val[i] ? er : E - 1;
    }

    // gather + duplicate-pack nc for 2 edges
    u64 nc[2][8];
#pragma unroll
    for (int i = 0; i < 2; i++) {
        const int s0 = ei[eidx[i]];
        const int s1 = ei[E + eidx[i]];
        const float4* p0 = (const float4*)(nf + (size_t)s0 * D);
        const float4* p1 = (const float4*)(nf + (size_t)s1 * D);
        float4 x0 = p0[0], x1 = p0[1], y0 = p1[0], y1 = p1[1];
        float n[8];
        n[0] = 0.5f * (x0.x + y0.x); n[1] = 0.5f * (x0.y + y0.y);
        n[2] = 0.5f * (x0.z + y0.z); n[3] = 0.5f * (x0.w + y0.w);
        n[4] = 0.5f * (x1.x + y1.x); n[5] = 0.5f * (x1.y + y1.y);
        n[6] = 0.5f * (x1.z + y1.z); n[7] = 0.5f * (x1.w + y1.w);
#pragma unroll
        for (int k = 0; k < 8; k++) nc[i][k] = pack2(n[k], n[k]);
    }

    u64 acc[2][8];
    const u64 z = pack2(0.f, 0.f);
#pragma unroll
    for (int i = 0; i < 2; i++)
#pragma unroll
        for (int d = 0; d < 8; d++) acc[i][d] = z;

#pragma unroll 1
    for (int jp = 0; jp < 128; jp++) {
        u64 w8[8];
        {
            ulonglong2 v0 = *(const ulonglong2*)&w2p[jp * 8 + 0];
            ulonglong2 v1 = *(const ulonglong2*)&w2p[jp * 8 + 2];
            ulonglong2 v2 = *(const ulonglong2*)&w2p[jp * 8 + 4];
            ulonglong2 v3 = *(const ulonglong2*)&w2p[jp * 8 + 6];
            w8[0] = v0.x; w8[1] = v0.y; w8[2] = v1.x; w8[3] = v1.y;
            w8[4] = v2.x; w8[5] = v2.y; w8[6] = v3.x; w8[7] = v3.y;
        }
        const u64 bp = b2ps[jp];
        // two independent 4-term chains per edge (RAW depth 4+1 instead of 8)
        u64 qa0 = ffma2(nc[0][0], w8[0], bp);
        u64 qb0 = ffma2(nc[0][4], w8[4], z);
        u64 qa1 = ffma2(nc[1][0], w8[0], bp);
        u64 qb1 = ffma2(nc[1][4], w8[4], z);
#pragma unroll
        for (int k = 1; k < 4; k++) {
            qa0 = ffma2(nc[0][k],     w8[k],     qa0);
            qb0 = ffma2(nc[0][k + 4], w8[k + 4], qb0);
            qa1 = ffma2(nc[1][k],     w8[k],     qa1);
            qb1 = ffma2(nc[1][k + 4], w8[k + 4], qb1);
        }
        u64 r0 = relu2x(fadd2(qa0, qb0));
        u64 r1 = relu2x(fadd2(qa1, qb1));

        u64 m8[8];
        {
            ulonglong2 v0 = *(const ulonglong2*)&ms2p[jp * 8 + 0];
            ulonglong2 v1 = *(const ulonglong2*)&ms2p[jp * 8 + 2];
            ulonglong2 v2 = *(const ulonglong2*)&ms2p[jp * 8 + 4];
            ulonglong2 v3 = *(const ulonglong2*)&ms2p[jp * 8 + 6];
            m8[0] = v0.x; m8[1] = v0.y; m8[2] = v1.x; m8[3] = v1.y;
            m8[4] = v2.x; m8[5] = v2.y; m8[6] = v3.x; m8[7] = v3.y;
        }
#pragma unroll
        for (int d = 0; d < 8; d++) {
            acc[0][d] = ffma2(r0, m8[d], acc[0][d]);
            acc[1][d] = ffma2(r1, m8[d], acc[1][d]);
        }
    }

#pragma unroll
    for (int i = 0; i < 2; i++) {
        if (!val[i]) continue;
        const float4* eap = (const float4*)(ea + (size_t)eidx[i] * D);
        float4 i0 = eap[0], i1 = eap[1];
        float o[8];
#pragma unroll
        for (int d = 0; d < 8; d++) {
            float2 p = unpack2(acc[i][d]);
            o[d] = p.x + p.y + c8s[d];
        }
        float4 o0 = make_float4(i0.x + o[0], i0.y + o[1], i0.z + o[2], i0.w + o[3]);
        float4 o1 = make_float4(i1.x + o[4], i1.y + o[5], i1.z + o[6], i1.w + o[7]);
        float4* op = (float4*)(out + (size_t)eidx[i] * D);
        op[0] = o0; op[1] = o1;
    }
}

// ---------------- launcher ----------------
extern "C" void kernel_launch(void* const* d_in, const int* in_sizes, int n_in,
                              void* d_out, int out_size) {
    const float* edge_attr     = (const float*)d_in[0];
    const float* node_features = (const float*)d_in[1];
    const int*   edge_index    = (const int*)  d_in[2];
    // d_in[3..8]: edge-encoder params — unused by the reference output
    const float* n_W1    = (const float*)d_in[9];
    const float* n_b1    = (const float*)d_in[10];
    const float* n_gamma = (const float*)d_in[11];
    const float* n_beta  = (const float*)d_in[12];
    const float* n_W2    = (const float*)d_in[13];
    const float* n_b2    = (const float*)d_in[14];
    const float* Wv      = (const float*)d_in[15];
    const float* bv      = (const float*)d_in[16];
    const float* Wo      = (const float*)d_in[17];
    const float* bo      = (const float*)d_in[18];
    const float* Wp      = (const float*)d_in[19];
    const float* bp      = (const float*)d_in[20];

    const int E = in_sizes[0] / D;
    float* out = (float*)d_out;

    k_fold1<<<16, 128>>>(Wo, Wp);
    k_fold2<<<16, 128>>>(Wv);
    k_fold3<<<16, 128>>>(n_W2, n_b2, bv, bo, bp, Wp);
    k_pass1<<<1184, 256>>>(node_features, edge_index, n_W1, n_b1, E);
    k_finalize<<<1, 256>>>(n_gamma, n_beta, 1.0f / (float)E);
    k_pass2<<<(E + 255) / 256, 128>>>(edge_attr, node_features, edge_index,
                                      n_W1, n_b1, out, E);
}

// round 10
// speedup vs baseline: 1.7383x; 1.4990x over previous
#include <cuda_runtime.h>
#include <cuda_fp16.h>

#define H 256
#define D 8
#define BN_EPS 1e-5f

typedef unsigned long long u64;
typedef unsigned int u32;

// ---------------- packed f32x2 helpers (pass1) ----------------
__device__ __forceinline__ u64 ffma2(u64 a, u64 b, u64 c) {
    u64 d; asm("fma.rn.f32x2 %0, %1, %2, %3;" : "=l"(d) : "l"(a), "l"(b), "l"(c)); return d;
}
__device__ __forceinline__ u64 fadd2(u64 a, u64 b) {
    u64 d; asm("add.rn.f32x2 %0, %1, %2;" : "=l"(d) : "l"(a), "l"(b)); return d;
}
__device__ __forceinline__ u64 pack2(float lo, float hi) {
    u64 d; asm("mov.b64 %0, {%1, %2};" : "=l"(d) : "f"(lo), "f"(hi)); return d;
}
__device__ __forceinline__ float2 unpack2(u64 v) {
    float lo, hi; asm("mov.b64 {%0, %1}, %2;" : "=f"(lo), "=f"(hi) : "l"(v));
    return make_float2(lo, hi);
}
__device__ __forceinline__ u64 abs2(u64 v) {
    u64 d; asm("and.b64 %0, %1, 0x7FFFFFFF7FFFFFFF;" : "=l"(d) : "l"(v)); return d;
}
__device__ __forceinline__ u64 relu2x(u64 q) { return fadd2(q, abs2(q)); }

// ---------------- mma helpers (pass2) ----------------
__device__ __forceinline__ void mma_16x8x8(
    float& d0, float& d1, float& d2, float& d3,
    u32 a0, u32 a1, u32 b0,
    float c0, float c1, float c2, float c3) {
    asm volatile("mma.sync.aligned.m16n8k8.row.col.f32.f16.f16.f32 "
        "{%0,%1,%2,%3}, {%4,%5}, {%6}, {%7,%8,%9,%10};"
        : "=f"(d0), "=f"(d1), "=f"(d2), "=f"(d3)
        : "r"(a0), "r"(a1), "r"(b0), "f"(c0), "f"(c1), "f"(c2), "f"(c3));
}
// pack {lo, hi} f16x2 (first operand of cvt goes to the UPPER half)
__device__ __forceinline__ u32 cvt_f16x2(float hi, float lo) {
    u32 d; asm("cvt.rn.f16x2.f32 %0, %1, %2;" : "=r"(d) : "f"(hi), "f"(lo)); return d;
}

// ---------------- device scratch (static, allocation-free) ----------------
__device__ float g_P [H * D];
__device__ float g_T2[H * D];
__device__ float g_M [H * D];
__device__ float g_c [D];
__device__ float g_sum  [H];
__device__ float g_sumsq[H];
__device__ float g_Ms[H * D];   // 0.5 * diag(s) @ M   (row-major [hidden][dout])
__device__ float g_c8[D];       // 0.5 * (t @ M + c)

// ---------------- fold kernels ----------------
__global__ void k_fold1(const float* __restrict__ Wo, const float* __restrict__ Wp) {
    int t = blockIdx.x * blockDim.x + threadIdx.x;
    int i = t >> 3, d = t & 7;
    float acc = 0.f;
#pragma unroll 8
    for (int k = 0; k < H; k++) acc = fmaf(Wo[i * H + k], Wp[k * D + d], acc);
    g_P[i * D + d] = acc;
    if (t < H) { g_sum[t] = 0.f; g_sumsq[t] = 0.f; }
}

__global__ void k_fold2(const float* __restrict__ Wv) {
    int t = blockIdx.x * blockDim.x + threadIdx.x;
    int i = t >> 3, d = t & 7;
    float acc = 0.f;
#pragma unroll 8
    for (int k = 0; k < H; k++) acc = fmaf(Wv[i * H + k], g_P[k * D + d], acc);
    g_T2[i * D + d] = acc;
}

__global__ void k_fold3(const float* __restrict__ W2, const float* __restrict__ b2,
                        const float* __restrict__ bv, const float* __restrict__ bo,
                        const float* __restrict__ bp, const float* __restrict__ Wp) {
    int t = blockIdx.x * blockDim.x + threadIdx.x;
    int i = t >> 3, d = t & 7;
    float acc = 0.f;
#pragma unroll 8
    for (int k = 0; k < H; k++) acc = fmaf(W2[i * H + k], g_T2[k * D + d], acc);
    g_M[i * D + d] = acc;
    if (t < D) {
        float c = bp[t];
        for (int k = 0; k < H; k++) {
            c = fmaf(b2[k], g_T2[k * D + t], c);
            c = fmaf(bv[k], g_P [k * D + t], c);
            c = fmaf(bo[k], Wp  [k * D + t], c);
        }
        g_c[t] = c;
    }
}

// ---------------- pass 1: batch statistics (R4-proven, unchanged) ----------------
__global__ void __launch_bounds__(256) k_pass1(
    const float* __restrict__ nf, const int* __restrict__ ei,
    const float* __restrict__ W1, const float* __restrict__ b1, int E) {
    __shared__ __align__(16) float ncsT[8][256];
    const int t = threadIdx.x;

    u64 w2[8];
#pragma unroll
    for (int k = 0; k < 8; k++) { float w = W1[k * H + t]; w2[k] = pack2(w, w); }
    const float bb = b1[t];
    const u64 b2p = pack2(bb, bb);

    u64 sumA = pack2(0.f, 0.f), ssqA = sumA, sumB = sumA, ssqB = sumA;
    const int numTiles = (E + 255) >> 8;

    for (int tile = blockIdx.x; tile < numTiles; tile += gridDim.x) {
        const int base = tile << 8;
        const int cnt  = min(256, E - base);
        __syncthreads();
        if (t < cnt) {
            const int e  = base + t;
            const int s0 = ei[e];
            const int s1 = ei[E + e];
            const float4* a = (const float4*)(nf + (size_t)s0 * D);
            const float4* b = (const float4*)(nf + (size_t)s1 * D);
            float4 x0 = a[0], x1 = a[1], y0 = b[0], y1 = b[1];
            ncsT[0][t] = 0.5f * (x0.x + y0.x);
            ncsT[1][t] = 0.5f * (x0.y + y0.y);
            ncsT[2][t] = 0.5f * (x0.z + y0.z);
            ncsT[3][t] = 0.5f * (x0.w + y0.w);
            ncsT[4][t] = 0.5f * (x1.x + y1.x);
            ncsT[5][t] = 0.5f * (x1.y + y1.y);
            ncsT[6][t] = 0.5f * (x1.z + y1.z);
            ncsT[7][t] = 0.5f * (x1.w + y1.w);
        }
        __syncthreads();
        int e = 0;
        for (; e + 3 < cnt; e += 4) {
            u64 q0 = b2p, q1 = b2p;
#pragma unroll
            for (int k = 0; k < 8; k++) {
                ulonglong2 n = *(const ulonglong2*)&ncsT[k][e];
                q0 = ffma2(n.x, w2[k], q0);
                q1 = ffma2(n.y, w2[k], q1);
            }
            u64 r0 = relu2x(q0);
            u64 r1 = relu2x(q1);
            sumA = fadd2(sumA, r0);      sumB = fadd2(sumB, r1);
            ssqA = ffma2(r0, r0, ssqA);  ssqB = ffma2(r1, r1, ssqB);
        }
        for (; e + 1 < cnt; e += 2) {
            u64 q0 = b2p;
#pragma unroll
            for (int k = 0; k < 8; k++)
                q0 = ffma2(*(const u64*)&ncsT[k][e], w2[k], q0);
            u64 r0 = relu2x(q0);
            sumA = fadd2(sumA, r0);
            ssqA = ffma2(r0, r0, ssqA);
        }
        if (e < cnt) {
            u64 q0 = pack2(bb, -1e30f);
#pragma unroll
            for (int k = 0; k < 8; k++)
                q0 = ffma2(pack2(ncsT[k][e], 0.f), w2[k], q0);
            u64 r0 = relu2x(q0);
            sumA = fadd2(sumA, r0);
            ssqA = ffma2(r0, r0, ssqA);
        }
    }
    float2 sa = unpack2(fadd2(sumA, sumB));
    float2 qa = unpack2(fadd2(ssqA, ssqB));
    atomicAdd(&g_sum[t],   sa.x + sa.y);      // Σ r  (r = 2h)
    atomicAdd(&g_sumsq[t], qa.x + qa.y);      // Σ r²
}

// ---------------- finalize: Ms = 0.5*s*M (pass2 uses plain relu) ----------------
__global__ void k_finalize(const float* __restrict__ gamma,
                           const float* __restrict__ beta, float invE) {
    __shared__ float tvs[H];
    const int j = threadIdx.x;
    float mu  = 0.5f  * g_sum[j]   * invE;              // E[h]
    float eh2 = 0.25f * g_sumsq[j] * invE;              // E[h^2]
    float var = fmaf(-mu, mu, eh2);
    float s   = gamma[j] * rsqrtf(var + BN_EPS);
    float tv  = fmaf(-mu, s, beta[j]);
#pragma unroll
    for (int d = 0; d < D; d++) g_Ms[j * D + d] = 0.5f * s * g_M[j * D + d];
    tvs[j] = tv;
    __syncthreads();
    if (j < D) {
        float acc = g_c[j];
        for (int k = 0; k < H; k++) acc = fmaf(tvs[k], g_M[k * D + j], acc);
        g_c8[j] = 0.5f * acc;
    }
}

// ---------------- pass 2 (tensor cores): out = ea + relu(nc@W1+b1)@Ms05 + c8 ----------------
// Warp-tile = 16 edges. GEMM1: m16(edges) x n8(hidden chunk) x k8(D), GEMM2:
// m16 x n8(dout) x k8(hidden chunk), D-frag of GEMM1 == A-frag of GEMM2.
__global__ void __launch_bounds__(256) k_pass2t(
    const float* __restrict__ ea, const float* __restrict__ nf,
    const int* __restrict__ ei,
    const float* __restrict__ W1, const float* __restrict__ b1,
    float* __restrict__ out, int E) {
    __shared__ u32    w1f[32][32];   // [chunk][lane]: B-frag of W1  {W1[k0][n], W1[k1][n]}
    __shared__ u32    msf[32][32];   // [chunk][lane]: B-frag of Ms  {Ms[j0][n], Ms[j1][n]}
    __shared__ float2 b1p[32][4];    // [chunk][lane%4]: bias pair
    __shared__ float2 c8p[4];        // [lane%4]: c8 pair

    const int t = threadIdx.x;
    for (int idx = t; idx < 1024; idx += 256) {
        int ch = idx >> 5, ln = idx & 31;
        int k0 = (ln & 3) * 2;        // k index pair (lo = even)
        int n  = ln >> 2;             // n index
        __half2 hw = __floats2half2_rn(W1[k0 * H + ch * 8 + n],
                                       W1[(k0 + 1) * H + ch * 8 + n]);
        w1f[ch][ln] = *(u32*)&hw;
        __half2 hm = __floats2half2_rn(g_Ms[(ch * 8 + k0) * D + n],
                                       g_Ms[(ch * 8 + k0 + 1) * D + n]);
        msf[ch][ln] = *(u32*)&hm;
    }
    for (int idx = t; idx < 128; idx += 256) {
        int ch = idx >> 2, q = idx & 3;
        b1p[ch][q] = make_float2(b1[ch * 8 + q * 2], b1[ch * 8 + q * 2 + 1]);
    }
    if (t < 4) c8p[t] = make_float2(g_c8[t * 2], g_c8[t * 2 + 1]);
    __syncthreads();

    const int lane = t & 31;
    const int gwarp = blockIdx.x * 8 + (t >> 5);
    const int nwarps = gridDim.x * 8;
    const int ntiles = (E + 15) >> 4;
    const int dcol = (lane & 3) * 2;        // dim pair (GEMM1 A) / dout pair (epilogue)

    for (int g = gwarp; g < ntiles; g += nwarps) {
        const int base = g << 4;
        const int r0 = base + (lane >> 2);
        const int r1 = r0 + 8;
        const int e0 = min(r0, E - 1);
        const int e1 = min(r1, E - 1);

        // A-fragment: nc[edge][dim pair] in fp16
        u32 a0, a1;
        {
            int s0 = ei[e0], s1 = ei[E + e0];
            float2 u = *(const float2*)(nf + (size_t)s0 * D + dcol);
            float2 v = *(const float2*)(nf + (size_t)s1 * D + dcol);
            a0 = cvt_f16x2(0.5f * (u.y + v.y), 0.5f * (u.x + v.x));
            int s2 = ei[e1], s3 = ei[E + e1];
            float2 p = *(const float2*)(nf + (size_t)s2 * D + dcol);
            float2 q = *(const float2*)(nf + (size_t)s3 * D + dcol);
            a1 = cvt_f16x2(0.5f * (p.y + q.y), 0.5f * (p.x + q.x));
        }

        // two accumulator sets (even/odd chunks) break the HMMA RAW chain
        float ae0 = 0.f, ae1 = 0.f, ae2 = 0.f, ae3 = 0.f;
        float ao0 = 0.f, ao1 = 0.f, ao2 = 0.f, ao3 = 0.f;

#pragma unroll 4
        for (int ch = 0; ch < 32; ch++) {
            u32 wb = w1f[ch][lane];
            float2 bb = b1p[ch][lane & 3];
            float q0, q1, q2, q3;
            mma_16x8x8(q0, q1, q2, q3, a0, a1, wb, bb.x, bb.y, bb.x, bb.y);
            q0 = fmaxf(q0, 0.f); q1 = fmaxf(q1, 0.f);
            q2 = fmaxf(q2, 0.f); q3 = fmaxf(q3, 0.f);
            u32 rh0 = cvt_f16x2(q1, q0);     // lo = even col
            u32 rh1 = cvt_f16x2(q3, q2);
            u32 mb = msf[ch][lane];
            if (ch & 1) mma_16x8x8(ao0, ao1, ao2, ao3, rh0, rh1, mb, ao0, ao1, ao2, ao3);
            else        mma_16x8x8(ae0, ae1, ae2, ae3, rh0, rh1, mb, ae0, ae1, ae2, ae3);
        }

        const float2 c8v = c8p[lane & 3];
        if (r0 < E) {
            float2 eav = *(const float2*)(ea + (size_t)r0 * D + dcol);
            float2 o = make_float2(eav.x + ae0 + ao0 + c8v.x,
                                   eav.y + ae1 + ao1 + c8v.y);
            *(float2*)(out + (size_t)r0 * D + dcol) = o;
        }
        if (r1 < E) {
            float2 eav = *(const float2*)(ea + (size_t)r1 * D + dcol);
            float2 o = make_float2(eav.x + ae2 + ao2 + c8v.x,
                                   eav.y + ae3 + ao3 + c8v.y);
            *(float2*)(out + (size_t)r1 * D + dcol) = o;
        }
    }
}

// ---------------- launcher ----------------
extern "C" void kernel_launch(void* const* d_in, const int* in_sizes, int n_in,
                              void* d_out, int out_size) {
    const float* edge_attr     = (const float*)d_in[0];
    const float* node_features = (const float*)d_in[1];
    const int*   edge_index    = (const int*)  d_in[2];
    // d_in[3..8]: edge-encoder params — unused by the reference output
    const float* n_W1    = (const float*)d_in[9];
    const float* n_b1    = (const float*)d_in[10];
    const float* n_gamma = (const float*)d_in[11];
    const float* n_beta  = (const float*)d_in[12];
    const float* n_W2    = (const float*)d_in[13];
    const float* n_b2    = (const float*)d_in[14];
    const float* Wv      = (const float*)d_in[15];
    const float* bv      = (const float*)d_in[16];
    const float* Wo      = (const float*)d_in[17];
    const float* bo      = (const float*)d_in[18];
    const float* Wp      = (const float*)d_in[19];
    const float* bp      = (const float*)d_in[20];

    const int E = in_sizes[0] / D;
    float* out = (float*)d_out;

    k_fold1<<<16, 128>>>(Wo, Wp);
    k_fold2<<<16, 128>>>(Wv);
    k_fold3<<<16, 128>>>(n_W2, n_b2, bv, bo, bp, Wp);
    k_pass1<<<1184, 256>>>(node_features, edge_index, n_W1, n_b1, E);
    k_finalize<<<1, 256>>>(n_gamma, n_beta, 1.0f / (float)E);
    k_pass2t<<<592, 256>>>(edge_attr, node_features, edge_index,
                           n_W1, n_b1, out, E);
}

// round 12
// speedup vs baseline: 2.1900x; 1.2598x over previous
#include <cuda_runtime.h>
#include <cuda_fp16.h>

#define H 256
#define D 8
#define BN_EPS 1e-5f

typedef unsigned long long u64;
typedef unsigned int u32;

// ---------------- mma helpers ----------------
__device__ __forceinline__ void mma_16x8x8(
    float& d0, float& d1, float& d2, float& d3,
    u32 a0, u32 a1, u32 b0,
    float c0, float c1, float c2, float c3) {
    asm volatile("mma.sync.aligned.m16n8k8.row.col.f32.f16.f16.f32 "
        "{%0,%1,%2,%3}, {%4,%5}, {%6}, {%7,%8,%9,%10};"
        : "=f"(d0), "=f"(d1), "=f"(d2), "=f"(d3)
        : "r"(a0), "r"(a1), "r"(b0), "f"(c0), "f"(c1), "f"(c2), "f"(c3));
}
// pack f16x2: lo goes to lower half
__device__ __forceinline__ u32 cvt_f16x2(float hi, float lo) {
    u32 d; asm("cvt.rn.f16x2.f32 %0, %1, %2;" : "=r"(d) : "f"(hi), "f"(lo)); return d;
}

// ---------------- device scratch (static, allocation-free) ----------------
__device__ float g_P [H * D];
__device__ float g_T2[H * D];
__device__ float g_M [H * D];
__device__ float g_c [D];
__device__ float g_sum  [H];    // Σ h   (h = relu(q), fp16-input based)
__device__ float g_sumsq[H];    // Σ h²
__device__ float g_Ms[H * D];   // 0.5 * diag(s) @ M
__device__ float g_c8[D];       // 0.5 * (t @ M + c)

// ---------------- fold kernels (proven) ----------------
__global__ void k_fold1(const float* __restrict__ Wo, const float* __restrict__ Wp) {
    int t = blockIdx.x * blockDim.x + threadIdx.x;
    int i = t >> 3, d = t & 7;
    float acc = 0.f;
#pragma unroll 8
    for (int k = 0; k < H; k++) acc = fmaf(Wo[i * H + k], Wp[k * D + d], acc);
    g_P[i * D + d] = acc;
    if (t < H) { g_sum[t] = 0.f; g_sumsq[t] = 0.f; }
}

__global__ void k_fold2(const float* __restrict__ Wv) {
    int t = blockIdx.x * blockDim.x + threadIdx.x;
    int i = t >> 3, d = t & 7;
    float acc = 0.f;
#pragma unroll 8
    for (int k = 0; k < H; k++) acc = fmaf(Wv[i * H + k], g_P[k * D + d], acc);
    g_T2[i * D + d] = acc;
}

__global__ void k_fold3(const float* __restrict__ W2, const float* __restrict__ b2,
                        const float* __restrict__ bv, const float* __restrict__ bo,
                        const float* __restrict__ bp, const float* __restrict__ Wp) {
    int t = blockIdx.x * blockDim.x + threadIdx.x;
    int i = t >> 3, d = t & 7;
    float acc = 0.f;
#pragma unroll 8
    for (int k = 0; k < H; k++) acc = fmaf(W2[i * H + k], g_T2[k * D + d], acc);
    g_M[i * D + d] = acc;
    if (t < D) {
        float c = bp[t];
        for (int k = 0; k < H; k++) {
            c = fmaf(b2[k], g_T2[k * D + t], c);
            c = fmaf(bv[k], g_P [k * D + t], c);
            c = fmaf(bo[k], Wp  [k * D + t], c);
        }
        g_c[t] = c;
    }
}

// ---------------- pass 1 (tensor cores): column sums of h and h^2 ----------------
// Block = 256 thr (8 warps). Tile = 256 edges staged as fp16 half2 in smem.
// Warp w owns hidden chunks [4w, 4w+4); W1 frags + biases live in registers.
__global__ void __launch_bounds__(256) k_pass1t(
    const float* __restrict__ nf, const int* __restrict__ ei,
    const float* __restrict__ W1, const float* __restrict__ b1, int E) {
    __shared__ __align__(16) uint4 ncs4[256];   // [edge]: 4 half2 = 8 fp16 dims
    const int t    = threadIdx.x;
    const int lane = t & 31;
    const int warp = t >> 5;
    const int q    = lane & 3;      // k/col-pair selector
    const int g    = lane >> 2;     // row-group selector

    // hoisted per-warp constants: B-frags of W1 and bias pairs for 4 chunks
    u32   wfrag[4];
    float bias0[4], bias1[4];
#pragma unroll
    for (int i = 0; i < 4; i++) {
        const int ch = warp * 4 + i;
        const int n  = ch * 8 + g;       // hidden col of this fragment element
        const int k0 = q * 2;            // dim pair
        wfrag[i] = cvt_f16x2(W1[(k0 + 1) * H + n], W1[k0 * H + n]);
        bias0[i] = b1[ch * 8 + q * 2];
        bias1[i] = b1[ch * 8 + q * 2 + 1];
    }

    float sum0[4], sum1[4], ssq0[4], ssq1[4];
#pragma unroll
    for (int i = 0; i < 4; i++) { sum0[i] = sum1[i] = ssq0[i] = ssq1[i] = 0.f; }

    const u32* ncsw = (const u32*)ncs4;
    const int numTiles = (E + 255) >> 8;

    for (int tile = blockIdx.x; tile < numTiles; tile += gridDim.x) {
        const int base = tile << 8;
        const int cnt  = min(256, E - base);
        __syncthreads();                  // protect ncs4 from prior readers
        {
            uint4 pk;
            if (t < cnt) {
                const int e  = base + t;
                const int s0 = ei[e];
                const int s1 = ei[E + e];
                const float4* a = (const float4*)(nf + (size_t)s0 * D);
                const float4* b = (const float4*)(nf + (size_t)s1 * D);
                float4 x0 = a[0], x1 = a[1], y0 = b[0], y1 = b[1];
                pk.x = cvt_f16x2(0.5f * (x0.y + y0.y), 0.5f * (x0.x + y0.x));
                pk.y = cvt_f16x2(0.5f * (x0.w + y0.w), 0.5f * (x0.z + y0.z));
                pk.z = cvt_f16x2(0.5f * (x1.y + y1.y), 0.5f * (x1.x + y1.x));
                pk.w = cvt_f16x2(0.5f * (x1.w + y1.w), 0.5f * (x1.z + y1.z));
            } else {
                pk = make_uint4(0, 0, 0, 0);
            }
            ncs4[t] = pk;
        }
        __syncthreads();

        if (cnt == 256) {                 // fast path: all rows valid
#pragma unroll 2
            for (int sub = 0; sub < 16; sub++) {
                const int r0 = sub * 16 + g;
                u32 a0 = ncsw[r0 * 4 + q];
                u32 a1 = ncsw[(r0 + 8) * 4 + q];
#pragma unroll
                for (int i = 0; i < 4; i++) {
                    float q0, q1, q2, q3;
                    mma_16x8x8(q0, q1, q2, q3, a0, a1, wfrag[i],
                               bias0[i], bias1[i], bias0[i], bias1[i]);
                    float h0 = fmaxf(q0, 0.f), h1 = fmaxf(q1, 0.f);
                    float h2 = fmaxf(q2, 0.f), h3 = fmaxf(q3, 0.f);
                    sum0[i] += h0 + h2;
                    sum1[i] += h1 + h3;
                    ssq0[i] = fmaf(h0, h0, fmaf(h2, h2, ssq0[i]));
                    ssq1[i] = fmaf(h1, h1, fmaf(h3, h3, ssq1[i]));
                }
            }
        } else {                          // tail tile: mask invalid rows
            const int nsub = (cnt + 15) >> 4;
            for (int sub = 0; sub < nsub; sub++) {
                const int r0 = sub * 16 + g;
                const float m0 = (r0 < cnt)     ? 1.f : 0.f;
                const float m1 = (r0 + 8 < cnt) ? 1.f : 0.f;
                u32 a0 = ncsw[r0 * 4 + q];
                u32 a1 = ncsw[(r0 + 8) * 4 + q];
#pragma unroll
                for (int i = 0; i < 4; i++) {
                    float q0, q1, q2, q3;
                    mma_16x8x8(q0, q1, q2, q3, a0, a1, wfrag[i],
                               bias0[i], bias1[i], bias0[i], bias1[i]);
                    float h0 = fmaxf(q0, 0.f) * m0, h1 = fmaxf(q1, 0.f) * m0;
                    float h2 = fmaxf(q2, 0.f) * m1, h3 = fmaxf(q3, 0.f) * m1;
                    sum0[i] += h0 + h2;
                    sum1[i] += h1 + h3;
                    ssq0[i] = fmaf(h0, h0, fmaf(h2, h2, ssq0[i]));
                    ssq1[i] = fmaf(h1, h1, fmaf(h3, h3, ssq1[i]));
                }
            }
        }
    }

    // reduce over row-groups (g = lane>>2) and emit per-column atomics
#pragma unroll
    for (int i = 0; i < 4; i++) {
#pragma unroll
        for (int off = 4; off < 32; off <<= 1) {
            sum0[i] += __shfl_xor_sync(0xFFFFFFFFu, sum0[i], off);
            sum1[i] += __shfl_xor_sync(0xFFFFFFFFu, sum1[i], off);
            ssq0[i] += __shfl_xor_sync(0xFFFFFFFFu, ssq0[i], off);
            ssq1[i] += __shfl_xor_sync(0xFFFFFFFFu, ssq1[i], off);
        }
        if (g == 0) {
            const int c0 = (warp * 4 + i) * 8 + q * 2;
            atomicAdd(&g_sum  [c0],     sum0[i]);
            atomicAdd(&g_sum  [c0 + 1], sum1[i]);
            atomicAdd(&g_sumsq[c0],     ssq0[i]);
            atomicAdd(&g_sumsq[c0 + 1], ssq1[i]);
        }
    }
}

// ---------------- finalize: sums are Σh, Σh² now ----------------
__global__ void k_finalize(const float* __restrict__ gamma,
                           const float* __restrict__ beta, float invE) {
    __shared__ float tvs[H];
    const int j = threadIdx.x;
    float mu  = g_sum[j]   * invE;
    float eh2 = g_sumsq[j] * invE;
    float var = fmaf(-mu, mu, eh2);
    float s   = gamma[j] * rsqrtf(var + BN_EPS);
    float tv  = fmaf(-mu, s, beta[j]);
#pragma unroll
    for (int d = 0; d < D; d++) g_Ms[j * D + d] = 0.5f * s * g_M[j * D + d];
    tvs[j] = tv;
    __syncthreads();
    if (j < D) {
        float acc = g_c[j];
        for (int k = 0; k < H; k++) acc = fmaf(tvs[k], g_M[k * D + j], acc);
        g_c8[j] = 0.5f * acc;
    }
}

// ---------------- pass 2 (tensor cores, R10-proven, unchanged) ----------------
__global__ void __launch_bounds__(256) k_pass2t(
    const float* __restrict__ ea, const float* __restrict__ nf,
    const int* __restrict__ ei,
    const float* __restrict__ W1, const float* __restrict__ b1,
    float* __restrict__ out, int E) {
    __shared__ u32    w1f[32][32];
    __shared__ u32    msf[32][32];
    __shared__ float2 b1p[32][4];
    __shared__ float2 c8p[4];

    const int t = threadIdx.x;
    for (int idx = t; idx < 1024; idx += 256) {
        int ch = idx >> 5, ln = idx & 31;
        int k0 = (ln & 3) * 2;
        int n  = ln >> 2;
        __half2 hw = __floats2half2_rn(W1[k0 * H + ch * 8 + n],
                                       W1[(k0 + 1) * H + ch * 8 + n]);
        w1f[ch][ln] = *(u32*)&hw;
        __half2 hm = __floats2half2_rn(g_Ms[(ch * 8 + k0) * D + n],
                                       g_Ms[(ch * 8 + k0 + 1) * D + n]);
        msf[ch][ln] = *(u32*)&hm;
    }
    for (int idx = t; idx < 128; idx += 256) {
        int ch = idx >> 2, qq = idx & 3;
        b1p[ch][qq] = make_float2(b1[ch * 8 + qq * 2], b1[ch * 8 + qq * 2 + 1]);
    }
    if (t < 4) c8p[t] = make_float2(g_c8[t * 2], g_c8[t * 2 + 1]);
    __syncthreads();

    const int lane = t & 31;
    const int gwarp = blockIdx.x * 8 + (t >> 5);
    const int nwarps = gridDim.x * 8;
    const int ntiles = (E + 15) >> 4;
    const int dcol = (lane & 3) * 2;

    for (int g = gwarp; g < ntiles; g += nwarps) {
        const int base = g << 4;
        const int r0 = base + (lane >> 2);
        const int r1 = r0 + 8;
        const int e0 = min(r0, E - 1);
        const int e1 = min(r1, E - 1);

        u32 a0, a1;
        {
            int s0 = ei[e0], s1 = ei[E + e0];
            float2 u = *(const float2*)(nf + (size_t)s0 * D + dcol);
            float2 v = *(const float2*)(nf + (size_t)s1 * D + dcol);
            a0 = cvt_f16x2(0.5f * (u.y + v.y), 0.5f * (u.x + v.x));
            int s2 = ei[e1], s3 = ei[E + e1];
            float2 p = *(const float2*)(nf + (size_t)s2 * D + dcol);
            float2 qv = *(const float2*)(nf + (size_t)s3 * D + dcol);
            a1 = cvt_f16x2(0.5f * (p.y + qv.y), 0.5f * (p.x + qv.x));
        }

        float ae0 = 0.f, ae1 = 0.f, ae2 = 0.f, ae3 = 0.f;
        float ao0 = 0.f, ao1 = 0.f, ao2 = 0.f, ao3 = 0.f;

#pragma unroll 4
        for (int ch = 0; ch < 32; ch++) {
            u32 wb = w1f[ch][lane];
            float2 bb = b1p[ch][lane & 3];
            float q0, q1, q2, q3;
            mma_16x8x8(q0, q1, q2, q3, a0, a1, wb, bb.x, bb.y, bb.x, bb.y);
            q0 = fmaxf(q0, 0.f); q1 = fmaxf(q1, 0.f);
            q2 = fmaxf(q2, 0.f); q3 = fmaxf(q3, 0.f);
            u32 rh0 = cvt_f16x2(q1, q0);
            u32 rh1 = cvt_f16x2(q3, q2);
            u32 mb = msf[ch][lane];
            if (ch & 1) mma_16x8x8(ao0, ao1, ao2, ao3, rh0, rh1, mb, ao0, ao1, ao2, ao3);
            else        mma_16x8x8(ae0, ae1, ae2, ae3, rh0, rh1, mb, ae0, ae1, ae2, ae3);
        }

        const float2 c8v = c8p[lane & 3];
        if (r0 < E) {
            float2 eav = *(const float2*)(ea + (size_t)r0 * D + dcol);
            float2 o = make_float2(eav.x + ae0 + ao0 + c8v.x,
                                   eav.y + ae1 + ao1 + c8v.y);
            *(float2*)(out + (size_t)r0 * D + dcol) = o;
        }
        if (r1 < E) {
            float2 eav = *(const float2*)(ea + (size_t)r1 * D + dcol);
            float2 o = make_float2(eav.x + ae2 + ao2 + c8v.x,
                                   eav.y + ae3 + ao3 + c8v.y);
            *(float2*)(out + (size_t)r1 * D + dcol) = o;
        }
    }
}

// ---------------- launcher ----------------
extern "C" void kernel_launch(void* const* d_in, const int* in_sizes, int n_in,
                              void* d_out, int out_size) {
    const float* edge_attr     = (const float*)d_in[0];
    const float* node_features = (const float*)d_in[1];
    const int*   edge_index    = (const int*)  d_in[2];
    // d_in[3..8]: edge-encoder params — unused by the reference output
    const float* n_W1    = (const float*)d_in[9];
    const float* n_b1    = (const float*)d_in[10];
    const float* n_gamma = (const float*)d_in[11];
    const float* n_beta  = (const float*)d_in[12];
    const float* n_W2    = (const float*)d_in[13];
    const float* n_b2    = (const float*)d_in[14];
    const float* Wv      = (const float*)d_in[15];
    const float* bv      = (const float*)d_in[16];
    const float* Wo      = (const float*)d_in[17];
    const float* bo      = (const float*)d_in[18];
    const float* Wp      = (const float*)d_in[19];
    const float* bp      = (const float*)d_in[20];

    const int E = in_sizes[0] / D;
    float* out = (float*)d_out;

    k_fold1<<<16, 128>>>(Wo, Wp);
    k_fold2<<<16, 128>>>(Wv);
    k_fold3<<<16, 128>>>(n_W2, n_b2, bv, bo, bp, Wp);
    k_pass1t<<<1184, 256>>>(node_features, edge_index, n_W1, n_b1, E);
    k_finalize<<<1, 256>>>(n_gamma, n_beta, 1.0f / (float)E);
    k_pass2t<<<592, 256>>>(edge_attr, node_features, edge_index,
                           n_W1, n_b1, out, E);
}

// round 14
// speedup vs baseline: 2.2386x; 1.0222x over previous
#include <cuda_runtime.h>
#include <cuda_fp16.h>

#define H 256
#define D 8
#define BN_EPS 1e-5f

typedef unsigned long long u64;
typedef unsigned int u32;

// ---------------- mma helpers ----------------
__device__ __forceinline__ void mma_16x8x8(
    float& d0, float& d1, float& d2, float& d3,
    u32 a0, u32 a1, u32 b0,
    float c0, float c1, float c2, float c3) {
    asm volatile("mma.sync.aligned.m16n8k8.row.col.f32.f16.f16.f32 "
        "{%0,%1,%2,%3}, {%4,%5}, {%6}, {%7,%8,%9,%10};"
        : "=f"(d0), "=f"(d1), "=f"(d2), "=f"(d3)
        : "r"(a0), "r"(a1), "r"(b0), "f"(c0), "f"(c1), "f"(c2), "f"(c3));
}
// pack f16x2: lo goes to lower half
__device__ __forceinline__ u32 cvt_f16x2(float hi, float lo) {
    u32 d; asm("cvt.rn.f16x2.f32 %0, %1, %2;" : "=r"(d) : "f"(hi), "f"(lo)); return d;
}

// ---------------- device scratch (static, allocation-free) ----------------
__device__ float g_P [H * D];
__device__ float g_T2[H * D];
__device__ float g_M [H * D];
__device__ float g_c [D];
__device__ float g_sum  [H];    // Σ h   (h = relu(q), fp16-input based)
__device__ float g_sumsq[H];    // Σ h²
__device__ float g_Ms[H * D];   // 0.5 * diag(s) @ M
__device__ float g_c8[D];       // 0.5 * (t @ M + c)

// ---------------- fold kernels (proven) ----------------
__global__ void k_fold1(const float* __restrict__ Wo, const float* __restrict__ Wp) {
    int t = blockIdx.x * blockDim.x + threadIdx.x;
    int i = t >> 3, d = t & 7;
    float acc = 0.f;
#pragma unroll 8
    for (int k = 0; k < H; k++) acc = fmaf(Wo[i * H + k], Wp[k * D + d], acc);
    g_P[i * D + d] = acc;
    if (t < H) { g_sum[t] = 0.f; g_sumsq[t] = 0.f; }
}

__global__ void k_fold2(const float* __restrict__ Wv) {
    int t = blockIdx.x * blockDim.x + threadIdx.x;
    int i = t >> 3, d = t & 7;
    float acc = 0.f;
#pragma unroll 8
    for (int k = 0; k < H; k++) acc = fmaf(Wv[i * H + k], g_P[k * D + d], acc);
    g_T2[i * D + d] = acc;
}

__global__ void k_fold3(const float* __restrict__ W2, const float* __restrict__ b2,
                        const float* __restrict__ bv, const float* __restrict__ bo,
                        const float* __restrict__ bp, const float* __restrict__ Wp) {
    int t = blockIdx.x * blockDim.x + threadIdx.x;
    int i = t >> 3, d = t & 7;
    float acc = 0.f;
#pragma unroll 8
    for (int k = 0; k < H; k++) acc = fmaf(W2[i * H + k], g_T2[k * D + d], acc);
    g_M[i * D + d] = acc;
    if (t < D) {
        float c = bp[t];
        for (int k = 0; k < H; k++) {
            c = fmaf(b2[k], g_T2[k * D + t], c);
            c = fmaf(bv[k], g_P [k * D + t], c);
            c = fmaf(bo[k], Wp  [k * D + t], c);
        }
        g_c[t] = c;
    }
}

// ---------------- pass 1 (tensor cores, R12-proven, unchanged) ----------------
__global__ void __launch_bounds__(256) k_pass1t(
    const float* __restrict__ nf, const int* __restrict__ ei,
    const float* __restrict__ W1, const float* __restrict__ b1, int E) {
    __shared__ __align__(16) uint4 ncs4[256];   // [edge]: 4 half2 = 8 fp16 dims
    const int t    = threadIdx.x;
    const int lane = t & 31;
    const int warp = t >> 5;
    const int q    = lane & 3;      // k/col-pair selector
    const int g    = lane >> 2;     // row-group selector

    u32   wfrag[4];
    float bias0[4], bias1[4];
#pragma unroll
    for (int i = 0; i < 4; i++) {
        const int ch = warp * 4 + i;
        const int n  = ch * 8 + g;
        const int k0 = q * 2;
        wfrag[i] = cvt_f16x2(W1[(k0 + 1) * H + n], W1[k0 * H + n]);
        bias0[i] = b1[ch * 8 + q * 2];
        bias1[i] = b1[ch * 8 + q * 2 + 1];
    }

    float sum0[4], sum1[4], ssq0[4], ssq1[4];
#pragma unroll
    for (int i = 0; i < 4; i++) { sum0[i] = sum1[i] = ssq0[i] = ssq1[i] = 0.f; }

    const u32* ncsw = (const u32*)ncs4;
    const int numTiles = (E + 255) >> 8;

    for (int tile = blockIdx.x; tile < numTiles; tile += gridDim.x) {
        const int base = tile << 8;
        const int cnt  = min(256, E - base);
        __syncthreads();
        {
            uint4 pk;
            if (t < cnt) {
                const int e  = base + t;
                const int s0 = ei[e];
                const int s1 = ei[E + e];
                const float4* a = (const float4*)(nf + (size_t)s0 * D);
                const float4* b = (const float4*)(nf + (size_t)s1 * D);
                float4 x0 = a[0], x1 = a[1], y0 = b[0], y1 = b[1];
                pk.x = cvt_f16x2(0.5f * (x0.y + y0.y), 0.5f * (x0.x + y0.x));
                pk.y = cvt_f16x2(0.5f * (x0.w + y0.w), 0.5f * (x0.z + y0.z));
                pk.z = cvt_f16x2(0.5f * (x1.y + y1.y), 0.5f * (x1.x + y1.x));
                pk.w = cvt_f16x2(0.5f * (x1.w + y1.w), 0.5f * (x1.z + y1.z));
            } else {
                pk = make_uint4(0, 0, 0, 0);
            }
            ncs4[t] = pk;
        }
        __syncthreads();

        if (cnt == 256) {
#pragma unroll 2
            for (int sub = 0; sub < 16; sub++) {
                const int r0 = sub * 16 + g;
                u32 a0 = ncsw[r0 * 4 + q];
                u32 a1 = ncsw[(r0 + 8) * 4 + q];
#pragma unroll
                for (int i = 0; i < 4; i++) {
                    float q0, q1, q2, q3;
                    mma_16x8x8(q0, q1, q2, q3, a0, a1, wfrag[i],
                               bias0[i], bias1[i], bias0[i], bias1[i]);
                    float h0 = fmaxf(q0, 0.f), h1 = fmaxf(q1, 0.f);
                    float h2 = fmaxf(q2, 0.f), h3 = fmaxf(q3, 0.f);
                    sum0[i] += h0 + h2;
                    sum1[i] += h1 + h3;
                    ssq0[i] = fmaf(h0, h0, fmaf(h2, h2, ssq0[i]));
                    ssq1[i] = fmaf(h1, h1, fmaf(h3, h3, ssq1[i]));
                }
            }
        } else {
            const int nsub = (cnt + 15) >> 4;
            for (int sub = 0; sub < nsub; sub++) {
                const int r0 = sub * 16 + g;
                const float m0 = (r0 < cnt)     ? 1.f : 0.f;
                const float m1 = (r0 + 8 < cnt) ? 1.f : 0.f;
                u32 a0 = ncsw[r0 * 4 + q];
                u32 a1 = ncsw[(r0 + 8) * 4 + q];
#pragma unroll
                for (int i = 0; i < 4; i++) {
                    float q0, q1, q2, q3;
                    mma_16x8x8(q0, q1, q2, q3, a0, a1, wfrag[i],
                               bias0[i], bias1[i], bias0[i], bias1[i]);
                    float h0 = fmaxf(q0, 0.f) * m0, h1 = fmaxf(q1, 0.f) * m0;
                    float h2 = fmaxf(q2, 0.f) * m1, h3 = fmaxf(q3, 0.f) * m1;
                    sum0[i] += h0 + h2;
                    sum1[i] += h1 + h3;
                    ssq0[i] = fmaf(h0, h0, fmaf(h2, h2, ssq0[i]));
                    ssq1[i] = fmaf(h1, h1, fmaf(h3, h3, ssq1[i]));
                }
            }
        }
    }

#pragma unroll
    for (int i = 0; i < 4; i++) {
#pragma unroll
        for (int off = 4; off < 32; off <<= 1) {
            sum0[i] += __shfl_xor_sync(0xFFFFFFFFu, sum0[i], off);
            sum1[i] += __shfl_xor_sync(0xFFFFFFFFu, sum1[i], off);
            ssq0[i] += __shfl_xor_sync(0xFFFFFFFFu, ssq0[i], off);
            ssq1[i] += __shfl_xor_sync(0xFFFFFFFFu, ssq1[i], off);
        }
        if (g == 0) {
            const int c0 = (warp * 4 + i) * 8 + q * 2;
            atomicAdd(&g_sum  [c0],     sum0[i]);
            atomicAdd(&g_sum  [c0 + 1], sum1[i]);
            atomicAdd(&g_sumsq[c0],     ssq0[i]);
            atomicAdd(&g_sumsq[c0 + 1], ssq1[i]);
        }
    }
}

// ---------------- finalize (R12-proven) ----------------
__global__ void k_finalize(const float* __restrict__ gamma,
                           const float* __restrict__ beta, float invE) {
    __shared__ float tvs[H];
    const int j = threadIdx.x;
    float mu  = g_sum[j]   * invE;
    float eh2 = g_sumsq[j] * invE;
    float var = fmaf(-mu, mu, eh2);
    float s   = gamma[j] * rsqrtf(var + BN_EPS);
    float tv  = fmaf(-mu, s, beta[j]);
#pragma unroll
    for (int d = 0; d < D; d++) g_Ms[j * D + d] = 0.5f * s * g_M[j * D + d];
    tvs[j] = tv;
    __syncthreads();
    if (j < D) {
        float acc = g_c[j];
        for (int k = 0; k < H; k++) acc = fmaf(tvs[k], g_M[k * D + j], acc);
        g_c8[j] = 0.5f * acc;
    }
}

// ---------------- pass 2 (tensor cores, 32 edges/warp-tile) ----------------
// Two m16 A-fragment groups per warp: 4 independent HMMA chains per chunk,
// per-chunk LDS amortized over 32 edges instead of 16.
__global__ void __launch_bounds__(256) k_pass2t(
    const float* __restrict__ ea, const float* __restrict__ nf,
    const int* __restrict__ ei,
    const float* __restrict__ W1, const float* __restrict__ b1,
    float* __restrict__ out, int E) {
    __shared__ u32    w1f[32][32];
    __shared__ u32    msf[32][32];
    __shared__ float2 b1p[32][4];
    __shared__ float2 c8p[4];

    const int t = threadIdx.x;
    for (int idx = t; idx < 1024; idx += 256) {
        int ch = idx >> 5, ln = idx & 31;
        int k0 = (ln & 3) * 2;
        int n  = ln >> 2;
        __half2 hw = __floats2half2_rn(W1[k0 * H + ch * 8 + n],
                                       W1[(k0 + 1) * H + ch * 8 + n]);
        w1f[ch][ln] = *(u32*)&hw;
        __half2 hm = __floats2half2_rn(g_Ms[(ch * 8 + k0) * D + n],
                                       g_Ms[(ch * 8 + k0 + 1) * D + n]);
        msf[ch][ln] = *(u32*)&hm;
    }
    for (int idx = t; idx < 128; idx += 256) {
        int ch = idx >> 2, qq = idx & 3;
        b1p[ch][qq] = make_float2(b1[ch * 8 + qq * 2], b1[ch * 8 + qq * 2 + 1]);
    }
    if (t < 4) c8p[t] = make_float2(g_c8[t * 2], g_c8[t * 2 + 1]);
    __syncthreads();

    const int lane = t & 31;
    const int gwarp = blockIdx.x * 8 + (t >> 5);
    const int nwarps = gridDim.x * 8;
    const int ntiles = (E + 31) >> 5;
    const int dcol = (lane & 3) * 2;

    for (int g = gwarp; g < ntiles; g += nwarps) {
        const int base = g << 5;
        int r[4];
        r[0] = base + (lane >> 2);
        r[1] = r[0] + 8;
        r[2] = r[0] + 16;
        r[3] = r[0] + 24;

        // A-fragments for 4 row groups (2 m16 tiles)
        u32 af[4];
#pragma unroll
        for (int j = 0; j < 4; j++) {
            const int e = min(r[j], E - 1);
            int s0 = ei[e], s1 = ei[E + e];
            float2 u = *(const float2*)(nf + (size_t)s0 * D + dcol);
            float2 v = *(const float2*)(nf + (size_t)s1 * D + dcol);
            af[j] = cvt_f16x2(0.5f * (u.y + v.y), 0.5f * (u.x + v.x));
        }

        // accumulators: group A (rows r0,r1) and group B (rows r2,r3), even/odd
        float Ae0 = 0.f, Ae1 = 0.f, Ae2 = 0.f, Ae3 = 0.f;
        float Ao0 = 0.f, Ao1 = 0.f, Ao2 = 0.f, Ao3 = 0.f;
        float Be0 = 0.f, Be1 = 0.f, Be2 = 0.f, Be3 = 0.f;
        float Bo0 = 0.f, Bo1 = 0.f, Bo2 = 0.f, Bo3 = 0.f;

#pragma unroll 4
        for (int ch = 0; ch < 32; ch++) {
            u32 wb = w1f[ch][lane];
            float2 bb = b1p[ch][lane & 3];
            float qa0, qa1, qa2, qa3, qb0, qb1, qb2, qb3;
            mma_16x8x8(qa0, qa1, qa2, qa3, af[0], af[1], wb, bb.x, bb.y, bb.x, bb.y);
            mma_16x8x8(qb0, qb1, qb2, qb3, af[2], af[3], wb, bb.x, bb.y, bb.x, bb.y);
            qa0 = fmaxf(qa0, 0.f); qa1 = fmaxf(qa1, 0.f);
            qa2 = fmaxf(qa2, 0.f); qa3 = fmaxf(qa3, 0.f);
            qb0 = fmaxf(qb0, 0.f); qb1 = fmaxf(qb1, 0.f);
            qb2 = fmaxf(qb2, 0.f); qb3 = fmaxf(qb3, 0.f);
            u32 ra0 = cvt_f16x2(qa1, qa0);
            u32 ra1 = cvt_f16x2(qa3, qa2);
            u32 rb0 = cvt_f16x2(qb1, qb0);
            u32 rb1 = cvt_f16x2(qb3, qb2);
            u32 mb = msf[ch][lane];
            if (ch & 1) {
                mma_16x8x8(Ao0, Ao1, Ao2, Ao3, ra0, ra1, mb, Ao0, Ao1, Ao2, Ao3);
                mma_16x8x8(Bo0, Bo1, Bo2, Bo3, rb0, rb1, mb, Bo0, Bo1, Bo2, Bo3);
            } else {
                mma_16x8x8(Ae0, Ae1, Ae2, Ae3, ra0, ra1, mb, Ae0, Ae1, Ae2, Ae3);
                mma_16x8x8(Be0, Be1, Be2, Be3, rb0, rb1, mb, Be0, Be1, Be2, Be3);
            }
        }

        const float2 c8v = c8p[lane & 3];
        float ox[4], oy[4];
        ox[0] = Ae0 + Ao0 + c8v.x; oy[0] = Ae1 + Ao1 + c8v.y;
        ox[1] = Ae2 + Ao2 + c8v.x; oy[1] = Ae3 + Ao3 + c8v.y;
        ox[2] = Be0 + Bo0 + c8v.x; oy[2] = Be1 + Bo1 + c8v.y;
        ox[3] = Be2 + Bo2 + c8v.x; oy[3] = Be3 + Bo3 + c8v.y;
#pragma unroll
        for (int j = 0; j < 4; j++) {
            if (r[j] < E) {
                float2 eav = *(const float2*)(ea + (size_t)r[j] * D + dcol);
                float2 o = make_float2(eav.x + ox[j], eav.y + oy[j]);
                *(float2*)(out + (size_t)r[j] * D + dcol) = o;
            }
        }
    }
}

// ---------------- launcher ----------------
extern "C" void kernel_launch(void* const* d_in, const int* in_sizes, int n_in,
                              void* d_out, int out_size) {
    const float* edge_attr     = (const float*)d_in[0];
    const float* node_features = (const float*)d_in[1];
    const int*   edge_index    = (const int*)  d_in[2];
    // d_in[3..8]: edge-encoder params — unused by the reference output
    const float* n_W1    = (const float*)d_in[9];
    const float* n_b1    = (const float*)d_in[10];
    const float* n_gamma = (const float*)d_in[11];
    const float* n_beta  = (const float*)d_in[12];
    const float* n_W2    = (const float*)d_in[13];
    const float* n_b2    = (const float*)d_in[14];
    const float* Wv      = (const float*)d_in[15];
    const float* bv      = (const float*)d_in[16];
    const float* Wo      = (const float*)d_in[17];
    const float* bo      = (const float*)d_in[18];
    const float* Wp      = (const float*)d_in[19];
    const float* bp      = (const float*)d_in[20];

    const int E = in_sizes[0] / D;
    float* out = (float*)d_out;

    k_fold1<<<16, 128>>>(Wo, Wp);
    k_fold2<<<16, 128>>>(Wv);
    k_fold3<<<16, 128>>>(n_W2, n_b2, bv, bo, bp, Wp);
    k_pass1t<<<1184, 256>>>(node_features, edge_index, n_W1, n_b1, E);
    k_finalize<<<1, 256>>>(n_gamma, n_beta, 1.0f / (float)E);
    k_pass2t<<<592, 256>>>(edge_attr, node_features, edge_index,
                           n_W1, n_b1, out, E);
}